// round 13
// baseline (speedup 1.0000x reference)
#include <cuda_runtime.h>
#include <math.h>
#include <stdint.h>

// ---------------- problem constants ----------------
#define BSZ    4
#define CIN    3
#define IMG    224
#define PATCH  16
#define DMODEL 384
#define DEPTH  4
#define NHEAD  8
#define HD     48
#define MLPD   1536
#define NCLS   5
#define TSTEPS 25
#define NTOK   196
#define ROWS   (BSZ*NTOK) // 784
#define HP     14
#define BETAF  0.9f
#define EPSF   1e-5f
#define SCALEF 0.14433756729740643f  // 48^-0.5
#define NCHUNK 28                     // 196 = 7*28

// ---------------- device state ----------------
__device__ float  g_h   [ROWS*DMODEL];
__device__ float  g_y   [ROWS*DMODEL];
__device__ float  g_xn  [ROWS*DMODEL];
__device__ float2 g_st  [ROWS];          // LN stats: (mean, inv)
__device__ float  g_q   [ROWS*DMODEL];
__device__ float  g_k   [ROWS*DMODEL];
__device__ float  g_v   [ROWS*DMODEL];
__device__ float  g_o   [ROWS*DMODEL];
__device__ float  g_s1  [ROWS*MLPD];
__device__ float  g_pool[BSZ*DMODEL];
__device__ float  g_mpe [ROWS*DMODEL];
__device__ float  g_mq  [DEPTH*ROWS*DMODEL];
__device__ float  g_mk  [DEPTH*ROWS*DMODEL];
__device__ float  g_mv  [DEPTH*ROWS*DMODEL];
__device__ float  g_m1  [DEPTH*ROWS*MLPD];
__device__ float  g_m2  [DEPTH*ROWS*DMODEL];
__device__ float  g_mh  [BSZ*NCLS];
__device__ float  g_acc [BSZ*NCLS];

// software grid barrier state
__device__ unsigned g_arrive;
__device__ unsigned g_gen;

__device__ __forceinline__ void gsync()
{
    __syncthreads();
    if (threadIdx.x == 0) {
        __threadfence();
        unsigned gen = *(volatile unsigned*)&g_gen;
        unsigned nb = gridDim.x;
        if (atomicAdd(&g_arrive, 1u) == nb - 1u) {
            g_arrive = 0u;
            __threadfence();
            *(volatile unsigned*)&g_gen = gen + 1u;
        } else {
            while (*(volatile unsigned*)&g_gen == gen) { }
        }
    }
    __syncthreads();
}

// ---------------- packed f32x2 helpers (each lane == __fmaf_rn) ----------------
__device__ __forceinline__ void ffma2(uint64_t& acc, uint64_t a, uint64_t b)
{
    asm("fma.rn.f32x2 %0, %1, %2, %0;" : "+l"(acc) : "l"(a), "l"(b));
}
__device__ __forceinline__ uint64_t pk2(float x)
{
    uint64_t r; asm("mov.b64 %0, {%1, %1};" : "=l"(r) : "f"(x)); return r;
}
__device__ __forceinline__ float2 upk(uint64_t v)
{
    float lo, hi; asm("mov.b64 {%0, %1}, %2;" : "=f"(lo), "=f"(hi) : "l"(v));
    return make_float2(lo, hi);
}

// LN application: exact XLA op order  ((v-mean)*inv)*g + b
__device__ __forceinline__ float lnap(float v, float2 st, float g, float b)
{
    return __fadd_rn(__fmul_rn(__fmul_rn(__fadd_rn(v, -st.x), st.y), g), b);
}

// ---------------- shared memory union ----------------
struct SmemU {
    union {
        float patch[CIN*PATCH*PATCH];                              // conv
        struct { float As[2][16][17]; float Bq[2][16][68];
                 float Bk[2][16][68]; float Bv[2][16][68]; } q;    // merged QKV ~28.3KB
        struct { float As[2][16][36];  float Bs[2][16][132]; } h;  // 32x128 MLP1
        struct { float As[2][32][17];  float Bs[2][32][68];  } w2; // 16x64 KC=32
        struct {
            unsigned long long qcb[NCHUNK];
            unsigned long long kbv[NTOK];
            unsigned long long vbv[NTOK];
            float af[NCHUNK][197];
        } a;                                                       // attn ~25.4KB
    };
};

// ---------------- epilogue ----------------
// MODE 0: LIF -> spike   MODE 1: yout += acc   MODE 2: LIF -> yout += spike
template<int MODE>
__device__ __forceinline__ void ep_one(int m, int n, int N, float vv,
        const float* __restrict__ scale, const float* __restrict__ bias,
        float* __restrict__ mem, float* __restrict__ spk, float* __restrict__ yout)
{
    size_t idx = (size_t)m*N + n;
    if (MODE == 1) {
        yout[idx] = __fadd_rn(yout[idx], vv);
    } else {
        vv = __fadd_rn(__fmul_rn(vv, scale[n]), bias[n]);
        float mm = __fadd_rn(__fmul_rn(BETAF, mem[idx]), vv);
        float s = (mm > 1.0f) ? 1.0f : 0.0f;
        mem[idx] = __fadd_rn(mm, -s);
        if (MODE == 0) spk[idx] = s;
        else           yout[idx] = __fadd_rn(yout[idx], s);
    }
}

// ---------------- merged QKV: 16x64 tile x3 matrices, LN applied on the fly ----------------
__device__ __forceinline__ void gemm_qkv(SmemU* sm,
        const float* __restrict__ y, const float2* __restrict__ stats,
        const float* __restrict__ lg, const float* __restrict__ lb,
        const float* __restrict__ Wq_l, const float* __restrict__ Wk_l, const float* __restrict__ Wv_l,
        int bm, int bn,
        const float* qs, const float* qb, float* mq, float* sq,
        const float* ks, const float* kb, float* mk, float* sk,
        const float* vs, const float* vb, float* mv, float* sv)
{
    const int tid = threadIdx.x;
    const int tx = tid & 15;
    const int my = tid >> 4;            // 0..15 (row within tile; always < ROWS)
    const int lrow = tid >> 2;          // 0..63
    const int lkq  = (tid & 3) << 2;
    const bool aload = (tid < 64);
    const int arow = bm + lrow;         // valid when aload (bm<=768, lrow<16)
    float2 st = aload ? stats[arow] : make_float2(0.f, 1.f);
    const float* yrow = y + (size_t)(aload ? arow : 0)*DMODEL;
    const float* bqp = Wq_l + (size_t)(bn + lrow)*DMODEL + lkq;
    const float* bkp = Wk_l + (size_t)(bn + lrow)*DMODEL + lkq;
    const float* bvp = Wv_l + (size_t)(bn + lrow)*DMODEL + lkq;

    uint64_t aq0=0ull, aq1=0ull, ak0=0ull, ak1=0ull, avv0=0ull, avv1=0ull;

    // chunk 0
    {
        if (aload) {
            float4 yv = *reinterpret_cast<const float4*>(yrow + lkq);
            float4 gv = *reinterpret_cast<const float4*>(lg + lkq);
            float4 bv = *reinterpret_cast<const float4*>(lb + lkq);
            sm->q.As[0][lkq+0][lrow] = lnap(yv.x, st, gv.x, bv.x);
            sm->q.As[0][lkq+1][lrow] = lnap(yv.y, st, gv.y, bv.y);
            sm->q.As[0][lkq+2][lrow] = lnap(yv.z, st, gv.z, bv.z);
            sm->q.As[0][lkq+3][lrow] = lnap(yv.w, st, gv.w, bv.w);
        }
        float4 q4 = *reinterpret_cast<const float4*>(bqp);
        float4 k4 = *reinterpret_cast<const float4*>(bkp);
        float4 v4 = *reinterpret_cast<const float4*>(bvp);
        sm->q.Bq[0][lkq+0][lrow]=q4.x; sm->q.Bq[0][lkq+1][lrow]=q4.y;
        sm->q.Bq[0][lkq+2][lrow]=q4.z; sm->q.Bq[0][lkq+3][lrow]=q4.w;
        sm->q.Bk[0][lkq+0][lrow]=k4.x; sm->q.Bk[0][lkq+1][lrow]=k4.y;
        sm->q.Bk[0][lkq+2][lrow]=k4.z; sm->q.Bk[0][lkq+3][lrow]=k4.w;
        sm->q.Bv[0][lkq+0][lrow]=v4.x; sm->q.Bv[0][lkq+1][lrow]=v4.y;
        sm->q.Bv[0][lkq+2][lrow]=v4.z; sm->q.Bv[0][lkq+3][lrow]=v4.w;
    }
    __syncthreads();

    const int nch = DMODEL >> 4;   // 24
    for (int c = 0; c < nch; c++) {
        const int buf = c & 1;
        const bool more = (c + 1 < nch);
        float4 na, q4, k4, v4;
        if (more) {
            int ko = (c+1)*16;
            if (aload) {
                float4 yv = *reinterpret_cast<const float4*>(yrow + ko + lkq);
                float4 gv = *reinterpret_cast<const float4*>(lg + ko + lkq);
                float4 bv = *reinterpret_cast<const float4*>(lb + ko + lkq);
                na.x = lnap(yv.x, st, gv.x, bv.x);
                na.y = lnap(yv.y, st, gv.y, bv.y);
                na.z = lnap(yv.z, st, gv.z, bv.z);
                na.w = lnap(yv.w, st, gv.w, bv.w);
            }
            q4 = *reinterpret_cast<const float4*>(bqp + ko);
            k4 = *reinterpret_cast<const float4*>(bkp + ko);
            v4 = *reinterpret_cast<const float4*>(bvp + ko);
        }
        #pragma unroll
        for (int kk = 0; kk < 16; kk++) {   // strictly ascending k
            uint64_t a = pk2(sm->q.As[buf][kk][my]);
            ulonglong2 bq = *reinterpret_cast<const ulonglong2*>(&sm->q.Bq[buf][kk][tx*4]);
            ulonglong2 bk = *reinterpret_cast<const ulonglong2*>(&sm->q.Bk[buf][kk][tx*4]);
            ulonglong2 bv = *reinterpret_cast<const ulonglong2*>(&sm->q.Bv[buf][kk][tx*4]);
            ffma2(aq0, a, bq.x);  ffma2(aq1, a, bq.y);
            ffma2(ak0, a, bk.x);  ffma2(ak1, a, bk.y);
            ffma2(avv0, a, bv.x); ffma2(avv1, a, bv.y);
        }
        if (more) {
            const int nbuf = buf ^ 1;
            if (aload) {
                sm->q.As[nbuf][lkq+0][lrow]=na.x; sm->q.As[nbuf][lkq+1][lrow]=na.y;
                sm->q.As[nbuf][lkq+2][lrow]=na.z; sm->q.As[nbuf][lkq+3][lrow]=na.w;
            }
            sm->q.Bq[nbuf][lkq+0][lrow]=q4.x; sm->q.Bq[nbuf][lkq+1][lrow]=q4.y;
            sm->q.Bq[nbuf][lkq+2][lrow]=q4.z; sm->q.Bq[nbuf][lkq+3][lrow]=q4.w;
            sm->q.Bk[nbuf][lkq+0][lrow]=k4.x; sm->q.Bk[nbuf][lkq+1][lrow]=k4.y;
            sm->q.Bk[nbuf][lkq+2][lrow]=k4.z; sm->q.Bk[nbuf][lkq+3][lrow]=k4.w;
            sm->q.Bv[nbuf][lkq+0][lrow]=v4.x; sm->q.Bv[nbuf][lkq+1][lrow]=v4.y;
            sm->q.Bv[nbuf][lkq+2][lrow]=v4.z; sm->q.Bv[nbuf][lkq+3][lrow]=v4.w;
        }
        __syncthreads();
    }

    const int m = bm + my;
    const int n0 = bn + tx*4;
    {
        float2 v01 = upk(aq0), v23 = upk(aq1);
        ep_one<0>(m, n0+0, DMODEL, v01.x, qs, qb, mq, sq, 0);
        ep_one<0>(m, n0+1, DMODEL, v01.y, qs, qb, mq, sq, 0);
        ep_one<0>(m, n0+2, DMODEL, v23.x, qs, qb, mq, sq, 0);
        ep_one<0>(m, n0+3, DMODEL, v23.y, qs, qb, mq, sq, 0);
    }
    {
        float2 v01 = upk(ak0), v23 = upk(ak1);
        ep_one<0>(m, n0+0, DMODEL, v01.x, ks, kb, mk, sk, 0);
        ep_one<0>(m, n0+1, DMODEL, v01.y, ks, kb, mk, sk, 0);
        ep_one<0>(m, n0+2, DMODEL, v23.x, ks, kb, mk, sk, 0);
        ep_one<0>(m, n0+3, DMODEL, v23.y, ks, kb, mk, sk, 0);
    }
    {
        float2 v01 = upk(avv0), v23 = upk(avv1);
        ep_one<0>(m, n0+0, DMODEL, v01.x, vs, vb, mv, sv, 0);
        ep_one<0>(m, n0+1, DMODEL, v01.y, vs, vb, mv, sv, 0);
        ep_one<0>(m, n0+2, DMODEL, v23.x, vs, vb, mv, sv, 0);
        ep_one<0>(m, n0+3, DMODEL, v23.y, vs, vb, mv, sv, 0);
    }
}

// ---------------- gemm 32x128 tile, 4x4 micro (FFMA2), LN-on-the-fly A (MLP1) ----------------
__device__ __forceinline__ void gemm_mlp1(SmemU* sm,
        const float* __restrict__ y, const float2* __restrict__ stats,
        const float* __restrict__ lg, const float* __restrict__ lb,
        const float* __restrict__ W, int bm, int bn,
        const float* __restrict__ scale, const float* __restrict__ bias,
        float* __restrict__ mem, float* __restrict__ spk)
{
    const int tid = threadIdx.x;
    const int tx = tid & 31;
    const int ty = tid >> 5;
    const int lrow = tid >> 2;
    const int lkq  = (tid & 3) << 2;
    const bool aload = (tid < 128);
    const int ar = bm + lrow;
    const bool aok = aload && (ar < ROWS);
    float2 st = aok ? stats[ar] : make_float2(0.f, 1.f);
    const float* yrow = y + (size_t)(aok ? ar : 0)*DMODEL;
    const float* bptr0 = W + (size_t)(bn + lrow)*DMODEL + lkq;
    const float* bptr1 = W + (size_t)(bn + 64 + lrow)*DMODEL + lkq;

    uint64_t accp[2][4];
    #pragma unroll
    for (int i = 0; i < 2; i++)
        #pragma unroll
        for (int j = 0; j < 4; j++) accp[i][j] = 0ull;

    {
        if (aload) {
            float4 na = make_float4(0.f,0.f,0.f,0.f);
            if (aok) {
                float4 yv = *reinterpret_cast<const float4*>(yrow + lkq);
                float4 gv = *reinterpret_cast<const float4*>(lg + lkq);
                float4 bv = *reinterpret_cast<const float4*>(lb + lkq);
                na.x = lnap(yv.x, st, gv.x, bv.x);
                na.y = lnap(yv.y, st, gv.y, bv.y);
                na.z = lnap(yv.z, st, gv.z, bv.z);
                na.w = lnap(yv.w, st, gv.w, bv.w);
            }
            sm->h.As[0][lkq+0][lrow]=na.x; sm->h.As[0][lkq+1][lrow]=na.y;
            sm->h.As[0][lkq+2][lrow]=na.z; sm->h.As[0][lkq+3][lrow]=na.w;
        }
        float4 bva = *reinterpret_cast<const float4*>(bptr0);
        float4 bvb = *reinterpret_cast<const float4*>(bptr1);
        sm->h.Bs[0][lkq+0][lrow]=bva.x;    sm->h.Bs[0][lkq+1][lrow]=bva.y;
        sm->h.Bs[0][lkq+2][lrow]=bva.z;    sm->h.Bs[0][lkq+3][lrow]=bva.w;
        sm->h.Bs[0][lkq+0][64+lrow]=bvb.x; sm->h.Bs[0][lkq+1][64+lrow]=bvb.y;
        sm->h.Bs[0][lkq+2][64+lrow]=bvb.z; sm->h.Bs[0][lkq+3][64+lrow]=bvb.w;
    }
    __syncthreads();

    const int nch = DMODEL >> 4;   // 24
    for (int c = 0; c < nch; c++) {
        const int buf = c & 1;
        const bool more = (c + 1 < nch);
        float4 na, b2a, b2b;
        if (more) {
            int ko = (c+1)*16;
            if (aload) {
                na = make_float4(0.f,0.f,0.f,0.f);
                if (aok) {
                    float4 yv = *reinterpret_cast<const float4*>(yrow + ko + lkq);
                    float4 gv = *reinterpret_cast<const float4*>(lg + ko + lkq);
                    float4 bv = *reinterpret_cast<const float4*>(lb + ko + lkq);
                    na.x = lnap(yv.x, st, gv.x, bv.x);
                    na.y = lnap(yv.y, st, gv.y, bv.y);
                    na.z = lnap(yv.z, st, gv.z, bv.z);
                    na.w = lnap(yv.w, st, gv.w, bv.w);
                }
            }
            b2a = *reinterpret_cast<const float4*>(bptr0 + ko);
            b2b = *reinterpret_cast<const float4*>(bptr1 + ko);
        }
        #pragma unroll
        for (int kk = 0; kk < 16; kk++) {
            ulonglong2 ap = *reinterpret_cast<const ulonglong2*>(&sm->h.As[buf][kk][ty*4]);
            float4 b = *reinterpret_cast<const float4*>(&sm->h.Bs[buf][kk][tx*4]);
            uint64_t bx = pk2(b.x), by = pk2(b.y), bz = pk2(b.z), bw = pk2(b.w);
            ffma2(accp[0][0], ap.x, bx); ffma2(accp[0][1], ap.x, by);
            ffma2(accp[0][2], ap.x, bz); ffma2(accp[0][3], ap.x, bw);
            ffma2(accp[1][0], ap.y, bx); ffma2(accp[1][1], ap.y, by);
            ffma2(accp[1][2], ap.y, bz); ffma2(accp[1][3], ap.y, bw);
        }
        if (more) {
            const int nbuf = buf ^ 1;
            if (aload) {
                sm->h.As[nbuf][lkq+0][lrow]=na.x; sm->h.As[nbuf][lkq+1][lrow]=na.y;
                sm->h.As[nbuf][lkq+2][lrow]=na.z; sm->h.As[nbuf][lkq+3][lrow]=na.w;
            }
            sm->h.Bs[nbuf][lkq+0][lrow]=b2a.x;    sm->h.Bs[nbuf][lkq+1][lrow]=b2a.y;
            sm->h.Bs[nbuf][lkq+2][lrow]=b2a.z;    sm->h.Bs[nbuf][lkq+3][lrow]=b2a.w;
            sm->h.Bs[nbuf][lkq+0][64+lrow]=b2b.x; sm->h.Bs[nbuf][lkq+1][64+lrow]=b2b.y;
            sm->h.Bs[nbuf][lkq+2][64+lrow]=b2b.z; sm->h.Bs[nbuf][lkq+3][64+lrow]=b2b.w;
        }
        __syncthreads();
    }
    #pragma unroll
    for (int rp = 0; rp < 2; rp++) {
        #pragma unroll
        for (int j = 0; j < 4; j++) {
            float2 v = upk(accp[rp][j]);
            int m0 = bm + ty*4 + rp*2;
            int n  = bn + tx*4 + j;
            if (m0 < ROWS)     ep_one<0>(m0,     n, MLPD, v.x, scale, bias, mem, spk, 0);
            if (m0 + 1 < ROWS) ep_one<0>(m0 + 1, n, MLPD, v.y, scale, bias, mem, spk, 0);
        }
    }
}

// ---------------- gemm 16x64 tile, KC=32, 1x4 micro (FFMA2) (Wo MODE1, MLP2 MODE2) ----------------
template<int MODE>
__device__ __forceinline__ void gemm_t16x64(SmemU* sm,
        const float* __restrict__ A, const float* __restrict__ W,
        int N, int K, int bm, int bn,
        const float* __restrict__ scale, const float* __restrict__ bias,
        float* __restrict__ mem, float* __restrict__ yout)
{
    const int tid = threadIdx.x;
    const int tx = tid & 15;
    const int my = tid >> 4;             // row 0..15
    const bool aload = (tid < 128);
    const int alrow = tid >> 3;          // 0..15
    const int alkq  = (tid & 7) << 2;    // 0..28
    const int blrow = tid >> 2;          // 0..63
    const int blkq  = (tid & 3) << 2;    // 0..12
    const float* aptr = A + (size_t)(bm + (aload ? alrow : 0))*K + alkq;
    const float* bptr = W + (size_t)(bn + blrow)*K + blkq;

    uint64_t acc01 = 0ull, acc23 = 0ull;

    {
        if (aload) {
            float4 av = *reinterpret_cast<const float4*>(aptr);
            sm->w2.As[0][alkq+0][alrow]=av.x; sm->w2.As[0][alkq+1][alrow]=av.y;
            sm->w2.As[0][alkq+2][alrow]=av.z; sm->w2.As[0][alkq+3][alrow]=av.w;
        }
        float4 b0 = *reinterpret_cast<const float4*>(bptr);
        float4 b1 = *reinterpret_cast<const float4*>(bptr + 16);
        sm->w2.Bs[0][blkq+0][blrow]=b0.x; sm->w2.Bs[0][blkq+1][blrow]=b0.y;
        sm->w2.Bs[0][blkq+2][blrow]=b0.z; sm->w2.Bs[0][blkq+3][blrow]=b0.w;
        sm->w2.Bs[0][16+blkq+0][blrow]=b1.x; sm->w2.Bs[0][16+blkq+1][blrow]=b1.y;
        sm->w2.Bs[0][16+blkq+2][blrow]=b1.z; sm->w2.Bs[0][16+blkq+3][blrow]=b1.w;
    }
    __syncthreads();

    const int nch = K >> 5;
    for (int c = 0; c < nch; c++) {
        const int buf = c & 1;
        const bool more = (c + 1 < nch);
        float4 av2, b20, b21;
        if (more) {
            int ko = (c+1)*32;
            if (aload) av2 = *reinterpret_cast<const float4*>(aptr + ko);
            b20 = *reinterpret_cast<const float4*>(bptr + ko);
            b21 = *reinterpret_cast<const float4*>(bptr + ko + 16);
        }
        #pragma unroll
        for (int kk = 0; kk < 32; kk++) {   // strictly ascending k
            uint64_t ad = pk2(sm->w2.As[buf][kk][my]);
            ulonglong2 bp = *reinterpret_cast<const ulonglong2*>(&sm->w2.Bs[buf][kk][tx*4]);
            ffma2(acc01, ad, bp.x);
            ffma2(acc23, ad, bp.y);
        }
        if (more) {
            const int nbuf = buf ^ 1;
            if (aload) {
                sm->w2.As[nbuf][alkq+0][alrow]=av2.x; sm->w2.As[nbuf][alkq+1][alrow]=av2.y;
                sm->w2.As[nbuf][alkq+2][alrow]=av2.z; sm->w2.As[nbuf][alkq+3][alrow]=av2.w;
            }
            sm->w2.Bs[nbuf][blkq+0][blrow]=b20.x; sm->w2.Bs[nbuf][blkq+1][blrow]=b20.y;
            sm->w2.Bs[nbuf][blkq+2][blrow]=b20.z; sm->w2.Bs[nbuf][blkq+3][blrow]=b20.w;
            sm->w2.Bs[nbuf][16+blkq+0][blrow]=b21.x; sm->w2.Bs[nbuf][16+blkq+1][blrow]=b21.y;
            sm->w2.Bs[nbuf][16+blkq+2][blrow]=b21.z; sm->w2.Bs[nbuf][16+blkq+3][blrow]=b21.w;
        }
        __syncthreads();
    }
    const int m = bm + my;   // 784 = 49*16, always valid
    float2 v01 = upk(acc01);
    float2 v23 = upk(acc23);
    ep_one<MODE>(m, bn + tx*4 + 0, N, v01.x, scale, bias, mem, 0, yout);
    ep_one<MODE>(m, bn + tx*4 + 1, N, v01.y, scale, bias, mem, 0, yout);
    ep_one<MODE>(m, bn + tx*4 + 2, N, v23.x, scale, bias, mem, 0, yout);
    ep_one<MODE>(m, bn + tx*4 + 3, N, v23.y, scale, bias, mem, 0, yout);
}

// ---------------- LN: stats only (XLA vectorized-reduce order) ----------------
__device__ __forceinline__ void ln_stats_warp(const float* __restrict__ rin, float2* __restrict__ outp)
{
    const unsigned fm = 0xffffffffu;
    int lane = threadIdx.x & 31;
    float a = 0.f;
    if (lane < 4) {
        for (int t2 = 0; t2 < 96; t2++) a = __fadd_rn(a, rin[4*t2 + lane]);
    }
    float a0 = __shfl_sync(fm, a, 0), a1 = __shfl_sync(fm, a, 1);
    float a2 = __shfl_sync(fm, a, 2), a3 = __shfl_sync(fm, a, 3);
    float mean = __fdiv_rn(__fadd_rn(__fadd_rn(a0, a2), __fadd_rn(a1, a3)), 384.0f);

    float b = 0.f;
    if (lane < 4) {
        for (int t2 = 0; t2 < 96; t2++) {
            float d = __fadd_rn(rin[4*t2 + lane], -mean);
            b = __fadd_rn(b, __fmul_rn(d, d));
        }
    }
    float b0 = __shfl_sync(fm, b, 0), b1 = __shfl_sync(fm, b, 1);
    float b2 = __shfl_sync(fm, b, 2), b3 = __shfl_sync(fm, b, 3);
    float var = __fdiv_rn(__fadd_rn(__fadd_rn(b0, b2), __fadd_rn(b1, b3)), 384.0f);
    float inv = __fdiv_rn(1.0f, __fsqrt_rn(__fadd_rn(var, EPSF)));
    if (lane == 0) *outp = make_float2(mean, inv);
}

// ---------------- full LN row (final LN only) ----------------
__device__ __forceinline__ void ln_row_warp(const float* __restrict__ rin,
        const float* __restrict__ g, const float* __restrict__ bta, float* __restrict__ out)
{
    const unsigned fm = 0xffffffffu;
    int lane = threadIdx.x & 31;
    float a = 0.f;
    if (lane < 4) {
        for (int t2 = 0; t2 < 96; t2++) a = __fadd_rn(a, rin[4*t2 + lane]);
    }
    float a0 = __shfl_sync(fm, a, 0), a1 = __shfl_sync(fm, a, 1);
    float a2 = __shfl_sync(fm, a, 2), a3 = __shfl_sync(fm, a, 3);
    float mean = __fdiv_rn(__fadd_rn(__fadd_rn(a0, a2), __fadd_rn(a1, a3)), 384.0f);

    float b = 0.f;
    if (lane < 4) {
        for (int t2 = 0; t2 < 96; t2++) {
            float d = __fadd_rn(rin[4*t2 + lane], -mean);
            b = __fadd_rn(b, __fmul_rn(d, d));
        }
    }
    float b0 = __shfl_sync(fm, b, 0), b1 = __shfl_sync(fm, b, 1);
    float b2 = __shfl_sync(fm, b, 2), b3 = __shfl_sync(fm, b, 3);
    float var = __fdiv_rn(__fadd_rn(__fadd_rn(b0, b2), __fadd_rn(b1, b3)), 384.0f);
    float inv = __fdiv_rn(1.0f, __fsqrt_rn(__fadd_rn(var, EPSF)));

    for (int d = lane; d < DMODEL; d += 32) {
        float dv = __fadd_rn(rin[d], -mean);
        out[d] = __fadd_rn(__fmul_rn(__fmul_rn(dv, inv), g[d]), bta[d]);
    }
}

// ---------------- patch-embed LIF + pos (strided range) ----------------
__device__ __forceinline__ void patch_lif_range(const float* __restrict__ pos, int start, int stride)
{
    for (int i = start; i < ROWS*DMODEL; i += stride) {
        float mm = __fadd_rn(__fmul_rn(BETAF, g_mpe[i]), g_h[i]);
        float s = (mm > 1.0f) ? 1.0f : 0.0f;
        g_mpe[i] = __fadd_rn(mm, -s);
        g_y[i] = __fadd_rn(s, pos[i % (NTOK*DMODEL)]);
    }
}

// ---------------- zero helper ----------------
__device__ __forceinline__ void zero_arr(float* p, int n, int gtid, int nth)
{
    for (int i = gtid; i < n; i += nth) p[i] = 0.f;
}

// ---------------- the megakernel ----------------
__global__ void __launch_bounds__(256, 2) mega(
    const float* __restrict__ x,      const float* __restrict__ conv_w,
    const float* __restrict__ bn0_s,  const float* __restrict__ bn0_b,
    const float* __restrict__ pos,
    const float* __restrict__ Wq,     const float* __restrict__ bnq_s, const float* __restrict__ bnq_b,
    const float* __restrict__ Wk,     const float* __restrict__ bnk_s, const float* __restrict__ bnk_b,
    const float* __restrict__ Wv,     const float* __restrict__ bnv_s, const float* __restrict__ bnv_b,
    const float* __restrict__ Wo,
    const float* __restrict__ ln1_g,  const float* __restrict__ ln1_b,
    const float* __restrict__ W1,     const float* __restrict__ bn1_s, const float* __restrict__ bn1_b,
    const float* __restrict__ W2,     const float* __restrict__ bn2_s, const float* __restrict__ bn2_b,
    const float* __restrict__ ln2_g,  const float* __restrict__ ln2_b,
    const float* __restrict__ lnf_g,  const float* __restrict__ lnf_b,
    const float* __restrict__ head_w, const float* __restrict__ head_b,
    float* __restrict__ out)
{
    __shared__ SmemU sm;
    const int nb  = gridDim.x;
    const int tid = threadIdx.x;
    const int wrp = tid >> 5;
    const int gtid = blockIdx.x * 256 + tid;
    const int nth  = nb * 256;

    // ---- zero persistent state ----
    zero_arr(g_mpe, ROWS*DMODEL, gtid, nth);
    zero_arr(g_mq,  DEPTH*ROWS*DMODEL, gtid, nth);
    zero_arr(g_mk,  DEPTH*ROWS*DMODEL, gtid, nth);
    zero_arr(g_mv,  DEPTH*ROWS*DMODEL, gtid, nth);
    zero_arr(g_m1,  DEPTH*ROWS*MLPD, gtid, nth);
    zero_arr(g_m2,  DEPTH*ROWS*DMODEL, gtid, nth);
    zero_arr(g_mh,  BSZ*NCLS, gtid, nth);
    zero_arr(g_acc, BSZ*NCLS, gtid, nth);

    // ---- conv patch embed (once); Eigen tap order (kh, kw, c), c minor ----
    for (int item = blockIdx.x; item < ROWS; item += nb) {
        int b = item / NTOK, n = item % NTOK;
        int py = n / HP, px = n % HP;
        for (int idx = tid; idx < 768; idx += 256) {
            int c = idx >> 8; int rem = idx & 255; int i = rem >> 4; int j = rem & 15;
            sm.patch[idx] = x[(((size_t)b*CIN + c)*IMG + (py*PATCH + i))*IMG + (px*PATCH + j)];
        }
        __syncthreads();
        for (int d = tid; d < DMODEL; d += 256) {
            const float* wr = conv_w + (size_t)d*768;
            float acc = 0.f;
            for (int i = 0; i < PATCH; i++)
                for (int j = 0; j < PATCH; j++)
                    #pragma unroll
                    for (int c = 0; c < CIN; c++) {
                        int off = c*256 + i*16 + j;
                        acc = __fmaf_rn(sm.patch[off], wr[off], acc);
                    }
            g_h[((size_t)b*NTOK + n)*DMODEL + d] = __fadd_rn(__fmul_rn(acc, bn0_s[d]), bn0_b[d]);
        }
        __syncthreads();
    }
    gsync();

    // ---- patch-LIF for t=0 ----
    patch_lif_range(pos, gtid, nth);
    gsync();

    // ---- timestep loop ----
    for (int t = 0; t < TSTEPS; t++) {
        for (int l = 0; l < DEPTH; l++) {
            const size_t wOff  = (size_t)l * DMODEL * DMODEL;
            const size_t w1Off = (size_t)l * MLPD * DMODEL;
            const size_t memD  = (size_t)l * ROWS * DMODEL;
            const size_t memM  = (size_t)l * ROWS * MLPD;
            const float* Wq_l = Wq + wOff;   const float* Wk_l = Wk + wOff;
            const float* Wv_l = Wv + wOff;   const float* Wo_l = Wo + wOff;
            const float* W1_l = W1 + w1Off;  const float* W2_l = W2 + w1Off;
            const float* qs = bnq_s + l*DMODEL, *qb2 = bnq_b + l*DMODEL;
            const float* ks = bnk_s + l*DMODEL, *kb2 = bnk_b + l*DMODEL;
            const float* vs = bnv_s + l*DMODEL, *vb2 = bnv_b + l*DMODEL;
            const float* m1s = bn1_s + l*MLPD,  *m1b = bn1_b + l*MLPD;
            const float* m2s = bn2_s + l*DMODEL, *m2b = bn2_b + l*DMODEL;

            // LN1 stats
            for (int row = blockIdx.x*8 + wrp; row < ROWS; row += nb*8)
                ln_stats_warp(g_y + (size_t)row*DMODEL, &g_st[row]);
            gsync();

            // merged QKV: 49x6 = 294 tiles of 16x64 x 3 matrices
            for (int t5 = blockIdx.x; t5 < 294; t5 += nb) {
                int bm = (t5 / 6) * 16, bn = (t5 % 6) * 64;
                gemm_qkv(&sm, g_y, g_st, ln1_g + l*DMODEL, ln1_b + l*DMODEL,
                         Wq_l, Wk_l, Wv_l, bm, bn,
                         qs, qb2, g_mq + memD, g_q,
                         ks, kb2, g_mk + memD, g_k,
                         vs, vb2, g_mv + memD, g_v);
            }
            gsync();

            // attention
            for (int item = blockIdx.x; item < 7*32; item += nb) {
                int chunk = item % 7;
                int bh = item / 7;
                int b = bh >> 3, h = bh & 7;
                int n0 = chunk * NCHUNK;
                __syncthreads();
                for (int tt = tid; tt < NTOK*2 + NCHUNK; tt += 256) {
                    int which, n;
                    if (tt < NTOK)        { which = 1; n = tt; }
                    else if (tt < 2*NTOK) { which = 2; n = tt - NTOK; }
                    else                  { which = 0; n = n0 + (tt - 2*NTOK); }
                    const float* src = (which == 0 ? g_q : (which == 1 ? g_k : g_v))
                                       + ((size_t)(b*NTOK + n))*DMODEL + h*HD;
                    unsigned long long bits = 0ull;
                    #pragma unroll
                    for (int j = 0; j < HD; j++)
                        if (src[j] != 0.f) bits |= (1ull << j);
                    if (which == 0)      sm.a.qcb[n - n0] = bits;
                    else if (which == 1) sm.a.kbv[n] = bits;
                    else                 sm.a.vbv[n] = bits;
                }
                __syncthreads();
                for (int idx = tid; idx < NCHUNK*NTOK; idx += 256) {
                    int cc = __popcll(sm.a.qcb[idx/NTOK] & sm.a.kbv[idx%NTOK]);
                    sm.a.af[idx/NTOK][idx%NTOK] = __fmul_rn((float)cc, SCALEF);
                }
                __syncthreads();
                {
                    float accv[6];
                    const float* af6[6];
                    int dd6[6];
                    int cnt = 0;
                    for (int it2 = tid; it2 < NCHUNK*HD; it2 += 256) {
                        af6[cnt] = sm.a.af[it2 / HD];
                        dd6[cnt] = it2 % HD;
                        accv[cnt] = 0.f;
                        cnt++;
                    }
                    for (int m = 0; m < NTOK; m++) {
                        unsigned long long vb = sm.a.vbv[m];
                        #pragma unroll
                        for (int i = 0; i < 6; i++) {
                            if (i < cnt) {
                                float a = af6[i][m];
                                if ((vb >> dd6[i]) & 1ull) accv[i] = __fadd_rn(accv[i], a);
                            }
                        }
                    }
                    int ci = 0;
                    for (int it2 = tid; it2 < NCHUNK*HD; it2 += 256) {
                        int n = it2 / HD, d = it2 % HD;
                        g_o[((size_t)(b*NTOK + n0 + n))*DMODEL + h*HD + d] = accv[ci++];
                    }
                }
                __syncthreads();
            }
            gsync();

            // Wo residual: 294 tiles of 16x64, KC=32
            for (int t5 = blockIdx.x; t5 < 294; t5 += nb) {
                int bm = (t5 / 6) * 16, bn = (t5 % 6) * 64;
                gemm_t16x64<1>(&sm, g_o, Wo_l, DMODEL, DMODEL, bm, bn, 0, 0, 0, g_y);
            }
            gsync();

            // LN2 stats
            for (int row = blockIdx.x*8 + wrp; row < ROWS; row += nb*8)
                ln_stats_warp(g_y + (size_t)row*DMODEL, &g_st[row]);
            gsync();

            // MLP1: 300 tiles of 32x128, LN2 on the fly
            for (int t5 = blockIdx.x; t5 < 300; t5 += nb) {
                int bm = (t5 / 12) * 32, bn = (t5 % 12) * 128;
                gemm_mlp1(&sm, g_y, g_st, ln2_g + l*DMODEL, ln2_b + l*DMODEL,
                          W1_l, bm, bn, m1s, m1b, g_m1 + memM, g_s1);
            }
            gsync();

            // MLP2: 294 tiles of 16x64, K=1536, KC=32
            for (int t5 = blockIdx.x; t5 < 294; t5 += nb) {
                int bm = (t5 / 6) * 16, bn = (t5 % 6) * 64;
                gemm_t16x64<2>(&sm, g_s1, W2_l, DMODEL, MLPD, bm, bn, m2s, m2b, g_m2 + memD, g_y);
            }
            gsync();
        }

        // final LN (full output into xn)
        for (int row = blockIdx.x*8 + wrp; row < ROWS; row += nb*8)
            ln_row_warp(g_y + (size_t)row*DMODEL, lnf_g, lnf_b, g_xn + (size_t)row*DMODEL);
        gsync();

        // token-mean pool (serial over n ascending)
        for (int it = gtid; it < BSZ*DMODEL; it += nth) {
            int b = it / DMODEL, d = it % DMODEL;
            float acc = 0.f;
            for (int n = 0; n < NTOK; n++)
                acc = __fadd_rn(acc, g_xn[((size_t)(b*NTOK + n))*DMODEL + d]);
            g_pool[it] = __fdiv_rn(acc, 196.0f);
        }
        gsync();

        // head logits + LIF (block 0) || patch-LIF for t+1 (other blocks)
        if (blockIdx.x == 0) {
            if (tid < BSZ*NCLS) {
                int b = tid / NCLS, c = tid % NCLS;
                float acc = 0.f;
                for (int d = 0; d < DMODEL; d++)
                    acc = __fmaf_rn(g_pool[b*DMODEL + d], head_w[d*NCLS + c], acc);
                float inp = __fadd_rn(acc, head_b[c]);
                float mm = __fadd_rn(__fmul_rn(BETAF, g_mh[tid]), inp);
                float s = (mm > 1.0f) ? 1.0f : 0.0f;
                g_mh[tid] = __fadd_rn(mm, -s);
                g_acc[tid] += s;
            }
        } else if (t + 1 < TSTEPS) {
            patch_lif_range(pos, (blockIdx.x - 1)*256 + tid, (nb - 1)*256);
        }
        gsync();
    }

    if (blockIdx.x == 0 && tid < BSZ*NCLS)
        out[tid] = __fdiv_rn(g_acc[tid], (float)TSTEPS);
}

// ---------------- host ----------------
extern "C" void kernel_launch(void* const* d_in, const int* in_sizes, int n_in,
                              void* d_out, int out_size)
{
    const float* x       = (const float*)d_in[0];
    const float* conv_w  = (const float*)d_in[1];
    const float* bn0_s   = (const float*)d_in[2];
    const float* bn0_b   = (const float*)d_in[3];
    const float* pos     = (const float*)d_in[4];
    const float* Wq      = (const float*)d_in[5];
    const float* bnq_s   = (const float*)d_in[6];
    const float* bnq_b   = (const float*)d_in[7];
    const float* Wk      = (const float*)d_in[8];
    const float* bnk_s   = (const float*)d_in[9];
    const float* bnk_b   = (const float*)d_in[10];
    const float* Wv      = (const float*)d_in[11];
    const float* bnv_s   = (const float*)d_in[12];
    const float* bnv_b   = (const float*)d_in[13];
    const float* Wo      = (const float*)d_in[14];
    const float* ln1_g   = (const float*)d_in[15];
    const float* ln1_b   = (const float*)d_in[16];
    const float* W1      = (const float*)d_in[17];
    const float* bn1_s   = (const float*)d_in[18];
    const float* bn1_b   = (const float*)d_in[19];
    const float* W2      = (const float*)d_in[20];
    const float* bn2_s   = (const float*)d_in[21];
    const float* bn2_b   = (const float*)d_in[22];
    const float* ln2_g   = (const float*)d_in[23];
    const float* ln2_b   = (const float*)d_in[24];
    const float* lnf_g   = (const float*)d_in[25];
    const float* lnf_b   = (const float*)d_in[26];
    const float* head_w  = (const float*)d_in[27];
    const float* head_b  = (const float*)d_in[28];
    float* out = (float*)d_out;

    int dev = 0;
    cudaGetDevice(&dev);
    int nsm = 0;
    cudaDeviceGetAttribute(&nsm, cudaDevAttrMultiProcessorCount, dev);
    int bpm = 0;
    cudaOccupancyMaxActiveBlocksPerMultiprocessor(&bpm, mega, 256, 0);
    if (bpm < 1) bpm = 1;
    if (bpm > 2) bpm = 2;
    int nblk = nsm * bpm;

    mega<<<nblk, 256>>>(x, conv_w, bn0_s, bn0_b, pos,
                        Wq, bnq_s, bnq_b, Wk, bnk_s, bnk_b, Wv, bnv_s, bnv_b, Wo,
                        ln1_g, ln1_b, W1, bn1_s, bn1_b, W2, bn2_s, bn2_b,
                        ln2_g, ln2_b, lnf_g, lnf_b, head_w, head_b, out);
}

// round 14
// speedup vs baseline: 1.0682x; 1.0682x over previous
#include <cuda_runtime.h>
#include <math.h>
#include <stdint.h>

// ---------------- problem constants ----------------
#define BSZ    4
#define CIN    3
#define IMG    224
#define PATCH  16
#define DMODEL 384
#define DEPTH  4
#define NHEAD  8
#define HD     48
#define MLPD   1536
#define NCLS   5
#define TSTEPS 25
#define NTOK   196
#define ROWS   (BSZ*NTOK) // 784
#define HP     14
#define BETAF  0.9f
#define EPSF   1e-5f
#define SCALEF 0.14433756729740643f  // 48^-0.5
#define NCHUNK 28                     // 196 = 7*28

// ---------------- device state ----------------
__device__ float  g_h   [ROWS*DMODEL];
__device__ float  g_y   [ROWS*DMODEL];
__device__ float  g_xn  [ROWS*DMODEL];
__device__ float2 g_st  [ROWS];          // LN stats: (mean, inv)
__device__ float  g_q   [ROWS*DMODEL];
__device__ float  g_k   [ROWS*DMODEL];
__device__ float  g_v   [ROWS*DMODEL];
__device__ float  g_o   [ROWS*DMODEL];
__device__ float  g_s1  [ROWS*MLPD];
__device__ float  g_pool[BSZ*DMODEL];
__device__ float  g_mpe [ROWS*DMODEL];
__device__ float  g_mq  [DEPTH*ROWS*DMODEL];
__device__ float  g_mk  [DEPTH*ROWS*DMODEL];
__device__ float  g_mv  [DEPTH*ROWS*DMODEL];
__device__ float  g_m1  [DEPTH*ROWS*MLPD];
__device__ float  g_m2  [DEPTH*ROWS*DMODEL];
__device__ float  g_mh  [BSZ*NCLS];
__device__ float  g_acc [BSZ*NCLS];

// software grid barrier state
__device__ unsigned g_arrive;
__device__ unsigned g_gen;

__device__ __forceinline__ void gsync()
{
    __syncthreads();
    if (threadIdx.x == 0) {
        __threadfence();
        unsigned gen = *(volatile unsigned*)&g_gen;
        unsigned nb = gridDim.x;
        if (atomicAdd(&g_arrive, 1u) == nb - 1u) {
            g_arrive = 0u;
            __threadfence();
            *(volatile unsigned*)&g_gen = gen + 1u;
        } else {
            while (*(volatile unsigned*)&g_gen == gen) { }
        }
    }
    __syncthreads();
}

// ---------------- packed f32x2 helpers (each lane == __fmaf_rn) ----------------
__device__ __forceinline__ void ffma2(uint64_t& acc, uint64_t a, uint64_t b)
{
    asm("fma.rn.f32x2 %0, %1, %2, %0;" : "+l"(acc) : "l"(a), "l"(b));
}
__device__ __forceinline__ uint64_t pk2(float x)
{
    uint64_t r; asm("mov.b64 %0, {%1, %1};" : "=l"(r) : "f"(x)); return r;
}
__device__ __forceinline__ float2 upk(uint64_t v)
{
    float lo, hi; asm("mov.b64 {%0, %1}, %2;" : "=f"(lo), "=f"(hi) : "l"(v));
    return make_float2(lo, hi);
}

// LN application: exact XLA op order  ((v-mean)*inv)*g + b
__device__ __forceinline__ float lnap(float v, float2 st, float g, float b)
{
    return __fadd_rn(__fmul_rn(__fmul_rn(__fadd_rn(v, -st.x), st.y), g), b);
}

// ---------------- shared memory union ----------------
struct SmemU {
    union {
        float patch[CIN*PATCH*PATCH];                              // conv
        struct { float As[2][16][68];  float Bs[2][16][68];  } g;  // 64x64 (QKV)
        struct { float As[2][16][36];  float Bs[2][16][132]; } h;  // 32x128 (MLP1)
        struct { float As[2][32][17];  float Bs[2][32][68];  } w2; // 16x64 KC=32
        struct {
            unsigned long long qcb[NCHUNK];
            unsigned long long kbv[NTOK];
            unsigned long long vbv[NTOK];
            float af[NCHUNK][197];
        } a;                                                       // attn ~25.4KB
    };
};

// ---------------- epilogue ----------------
// MODE 0: LIF -> spike   MODE 1: yout += acc   MODE 2: LIF -> yout += spike
template<int MODE>
__device__ __forceinline__ void ep_one(int m, int n, int N, float vv,
        const float* __restrict__ scale, const float* __restrict__ bias,
        float* __restrict__ mem, float* __restrict__ spk, float* __restrict__ yout)
{
    size_t idx = (size_t)m*N + n;
    if (MODE == 1) {
        yout[idx] = __fadd_rn(yout[idx], vv);
    } else {
        vv = __fadd_rn(__fmul_rn(vv, scale[n]), bias[n]);
        float mm = __fadd_rn(__fmul_rn(BETAF, mem[idx]), vv);
        float s = (mm > 1.0f) ? 1.0f : 0.0f;
        mem[idx] = __fadd_rn(mm, -s);
        if (MODE == 0) spk[idx] = s;
        else           yout[idx] = __fadd_rn(yout[idx], s);
    }
}

// ---------------- gemm 64x64 tile, 4x4 micro (FFMA2), LN-on-the-fly A (QKV) ----------------
__device__ __forceinline__ void gemm_t64_ln(SmemU* sm,
        const float* __restrict__ y, const float2* __restrict__ stats,
        const float* __restrict__ lg, const float* __restrict__ lb,
        const float* __restrict__ W, int bm, int bn,
        const float* __restrict__ scale, const float* __restrict__ bias,
        float* __restrict__ mem, float* __restrict__ spk)
{
    const int tid = threadIdx.x;
    const int tx = tid & 15;
    const int ty = tid >> 4;
    const int lr = tid >> 2;         // 0..63
    const int lk = (tid & 3) << 2;   // 0,4,8,12
    const int ar = bm + lr;
    const bool aok = (ar < ROWS);
    float2 st = aok ? stats[ar] : make_float2(0.f, 1.f);
    const float* yrow = y + (size_t)(aok ? ar : 0)*DMODEL;
    const float* bptr = W + (size_t)(bn + lr)*DMODEL + lk;

    uint64_t accp[2][4];
    #pragma unroll
    for (int i = 0; i < 2; i++)
        #pragma unroll
        for (int j = 0; j < 4; j++) accp[i][j] = 0ull;

    // chunk 0
    {
        float4 na = make_float4(0.f,0.f,0.f,0.f);
        if (aok) {
            float4 yv = *reinterpret_cast<const float4*>(yrow + lk);
            float4 gv = *reinterpret_cast<const float4*>(lg + lk);
            float4 bv = *reinterpret_cast<const float4*>(lb + lk);
            na.x = lnap(yv.x, st, gv.x, bv.x);
            na.y = lnap(yv.y, st, gv.y, bv.y);
            na.z = lnap(yv.z, st, gv.z, bv.z);
            na.w = lnap(yv.w, st, gv.w, bv.w);
        }
        sm->g.As[0][lk+0][lr]=na.x; sm->g.As[0][lk+1][lr]=na.y;
        sm->g.As[0][lk+2][lr]=na.z; sm->g.As[0][lk+3][lr]=na.w;
        float4 bv4 = *reinterpret_cast<const float4*>(bptr);
        sm->g.Bs[0][lk+0][lr]=bv4.x; sm->g.Bs[0][lk+1][lr]=bv4.y;
        sm->g.Bs[0][lk+2][lr]=bv4.z; sm->g.Bs[0][lk+3][lr]=bv4.w;
    }
    __syncthreads();

    const int nch = DMODEL >> 4;   // 24
    for (int c = 0; c < nch; c++) {
        const int buf = c & 1;
        const bool more = (c + 1 < nch);
        float4 na, bv2;
        if (more) {
            int ko = (c+1)*16;
            na = make_float4(0.f,0.f,0.f,0.f);
            if (aok) {
                float4 yv = *reinterpret_cast<const float4*>(yrow + ko + lk);
                float4 gv = *reinterpret_cast<const float4*>(lg + ko + lk);
                float4 bv = *reinterpret_cast<const float4*>(lb + ko + lk);
                na.x = lnap(yv.x, st, gv.x, bv.x);
                na.y = lnap(yv.y, st, gv.y, bv.y);
                na.z = lnap(yv.z, st, gv.z, bv.z);
                na.w = lnap(yv.w, st, gv.w, bv.w);
            }
            bv2 = *reinterpret_cast<const float4*>(bptr + ko);
        }
        #pragma unroll
        for (int kk = 0; kk < 16; kk++) {   // strictly ascending k
            ulonglong2 ap = *reinterpret_cast<const ulonglong2*>(&sm->g.As[buf][kk][ty*4]);
            float4 b = *reinterpret_cast<const float4*>(&sm->g.Bs[buf][kk][tx*4]);
            uint64_t bx = pk2(b.x), by = pk2(b.y), bz = pk2(b.z), bw = pk2(b.w);
            ffma2(accp[0][0], ap.x, bx); ffma2(accp[0][1], ap.x, by);
            ffma2(accp[0][2], ap.x, bz); ffma2(accp[0][3], ap.x, bw);
            ffma2(accp[1][0], ap.y, bx); ffma2(accp[1][1], ap.y, by);
            ffma2(accp[1][2], ap.y, bz); ffma2(accp[1][3], ap.y, bw);
        }
        if (more) {
            const int nbuf = buf ^ 1;
            sm->g.As[nbuf][lk+0][lr]=na.x; sm->g.As[nbuf][lk+1][lr]=na.y;
            sm->g.As[nbuf][lk+2][lr]=na.z; sm->g.As[nbuf][lk+3][lr]=na.w;
            sm->g.Bs[nbuf][lk+0][lr]=bv2.x; sm->g.Bs[nbuf][lk+1][lr]=bv2.y;
            sm->g.Bs[nbuf][lk+2][lr]=bv2.z; sm->g.Bs[nbuf][lk+3][lr]=bv2.w;
        }
        __syncthreads();
    }
    #pragma unroll
    for (int rp = 0; rp < 2; rp++) {
        #pragma unroll
        for (int j = 0; j < 4; j++) {
            float2 v = upk(accp[rp][j]);
            int m0 = bm + ty*4 + rp*2;
            int n  = bn + tx*4 + j;
            if (m0 < ROWS)     ep_one<0>(m0,     n, DMODEL, v.x, scale, bias, mem, spk, 0);
            if (m0 + 1 < ROWS) ep_one<0>(m0 + 1, n, DMODEL, v.y, scale, bias, mem, spk, 0);
        }
    }
}

// ---------------- gemm 32x128 tile, 4x4 micro (FFMA2), LN-on-the-fly A (MLP1) ----------------
__device__ __forceinline__ void gemm_mlp1(SmemU* sm,
        const float* __restrict__ y, const float2* __restrict__ stats,
        const float* __restrict__ lg, const float* __restrict__ lb,
        const float* __restrict__ W, int bm, int bn,
        const float* __restrict__ scale, const float* __restrict__ bias,
        float* __restrict__ mem, float* __restrict__ spk)
{
    const int tid = threadIdx.x;
    const int tx = tid & 31;
    const int ty = tid >> 5;
    const int lrow = tid >> 2;
    const int lkq  = (tid & 3) << 2;
    const bool aload = (tid < 128);
    const int ar = bm + lrow;
    const bool aok = aload && (ar < ROWS);
    float2 st = aok ? stats[ar] : make_float2(0.f, 1.f);
    const float* yrow = y + (size_t)(aok ? ar : 0)*DMODEL;
    const float* bptr0 = W + (size_t)(bn + lrow)*DMODEL + lkq;
    const float* bptr1 = W + (size_t)(bn + 64 + lrow)*DMODEL + lkq;

    uint64_t accp[2][4];
    #pragma unroll
    for (int i = 0; i < 2; i++)
        #pragma unroll
        for (int j = 0; j < 4; j++) accp[i][j] = 0ull;

    {
        if (aload) {
            float4 na = make_float4(0.f,0.f,0.f,0.f);
            if (aok) {
                float4 yv = *reinterpret_cast<const float4*>(yrow + lkq);
                float4 gv = *reinterpret_cast<const float4*>(lg + lkq);
                float4 bv = *reinterpret_cast<const float4*>(lb + lkq);
                na.x = lnap(yv.x, st, gv.x, bv.x);
                na.y = lnap(yv.y, st, gv.y, bv.y);
                na.z = lnap(yv.z, st, gv.z, bv.z);
                na.w = lnap(yv.w, st, gv.w, bv.w);
            }
            sm->h.As[0][lkq+0][lrow]=na.x; sm->h.As[0][lkq+1][lrow]=na.y;
            sm->h.As[0][lkq+2][lrow]=na.z; sm->h.As[0][lkq+3][lrow]=na.w;
        }
        float4 bva = *reinterpret_cast<const float4*>(bptr0);
        float4 bvb = *reinterpret_cast<const float4*>(bptr1);
        sm->h.Bs[0][lkq+0][lrow]=bva.x;    sm->h.Bs[0][lkq+1][lrow]=bva.y;
        sm->h.Bs[0][lkq+2][lrow]=bva.z;    sm->h.Bs[0][lkq+3][lrow]=bva.w;
        sm->h.Bs[0][lkq+0][64+lrow]=bvb.x; sm->h.Bs[0][lkq+1][64+lrow]=bvb.y;
        sm->h.Bs[0][lkq+2][64+lrow]=bvb.z; sm->h.Bs[0][lkq+3][64+lrow]=bvb.w;
    }
    __syncthreads();

    const int nch = DMODEL >> 4;   // 24
    for (int c = 0; c < nch; c++) {
        const int buf = c & 1;
        const bool more = (c + 1 < nch);
        float4 na, b2a, b2b;
        if (more) {
            int ko = (c+1)*16;
            if (aload) {
                na = make_float4(0.f,0.f,0.f,0.f);
                if (aok) {
                    float4 yv = *reinterpret_cast<const float4*>(yrow + ko + lkq);
                    float4 gv = *reinterpret_cast<const float4*>(lg + ko + lkq);
                    float4 bv = *reinterpret_cast<const float4*>(lb + ko + lkq);
                    na.x = lnap(yv.x, st, gv.x, bv.x);
                    na.y = lnap(yv.y, st, gv.y, bv.y);
                    na.z = lnap(yv.z, st, gv.z, bv.z);
                    na.w = lnap(yv.w, st, gv.w, bv.w);
                }
            }
            b2a = *reinterpret_cast<const float4*>(bptr0 + ko);
            b2b = *reinterpret_cast<const float4*>(bptr1 + ko);
        }
        #pragma unroll
        for (int kk = 0; kk < 16; kk++) {
            ulonglong2 ap = *reinterpret_cast<const ulonglong2*>(&sm->h.As[buf][kk][ty*4]);
            float4 b = *reinterpret_cast<const float4*>(&sm->h.Bs[buf][kk][tx*4]);
            uint64_t bx = pk2(b.x), by = pk2(b.y), bz = pk2(b.z), bw = pk2(b.w);
            ffma2(accp[0][0], ap.x, bx); ffma2(accp[0][1], ap.x, by);
            ffma2(accp[0][2], ap.x, bz); ffma2(accp[0][3], ap.x, bw);
            ffma2(accp[1][0], ap.y, bx); ffma2(accp[1][1], ap.y, by);
            ffma2(accp[1][2], ap.y, bz); ffma2(accp[1][3], ap.y, bw);
        }
        if (more) {
            const int nbuf = buf ^ 1;
            if (aload) {
                sm->h.As[nbuf][lkq+0][lrow]=na.x; sm->h.As[nbuf][lkq+1][lrow]=na.y;
                sm->h.As[nbuf][lkq+2][lrow]=na.z; sm->h.As[nbuf][lkq+3][lrow]=na.w;
            }
            sm->h.Bs[nbuf][lkq+0][lrow]=b2a.x;    sm->h.Bs[nbuf][lkq+1][lrow]=b2a.y;
            sm->h.Bs[nbuf][lkq+2][lrow]=b2a.z;    sm->h.Bs[nbuf][lkq+3][lrow]=b2a.w;
            sm->h.Bs[nbuf][lkq+0][64+lrow]=b2b.x; sm->h.Bs[nbuf][lkq+1][64+lrow]=b2b.y;
            sm->h.Bs[nbuf][lkq+2][64+lrow]=b2b.z; sm->h.Bs[nbuf][lkq+3][64+lrow]=b2b.w;
        }
        __syncthreads();
    }
    #pragma unroll
    for (int rp = 0; rp < 2; rp++) {
        #pragma unroll
        for (int j = 0; j < 4; j++) {
            float2 v = upk(accp[rp][j]);
            int m0 = bm + ty*4 + rp*2;
            int n  = bn + tx*4 + j;
            if (m0 < ROWS)     ep_one<0>(m0,     n, MLPD, v.x, scale, bias, mem, spk, 0);
            if (m0 + 1 < ROWS) ep_one<0>(m0 + 1, n, MLPD, v.y, scale, bias, mem, spk, 0);
        }
    }
}

// ---------------- gemm 16x64 tile, KC=32, 1x4 micro (FFMA2) (Wo MODE1, MLP2 MODE2) ----------------
template<int MODE>
__device__ __forceinline__ void gemm_t16x64(SmemU* sm,
        const float* __restrict__ A, const float* __restrict__ W,
        int N, int K, int bm, int bn,
        const float* __restrict__ scale, const float* __restrict__ bias,
        float* __restrict__ mem, float* __restrict__ yout)
{
    const int tid = threadIdx.x;
    const int tx = tid & 15;
    const int my = tid >> 4;             // row 0..15
    const bool aload = (tid < 128);
    const int alrow = tid >> 3;          // 0..15
    const int alkq  = (tid & 7) << 2;    // 0..28
    const int blrow = tid >> 2;          // 0..63
    const int blkq  = (tid & 3) << 2;    // 0..12
    const float* aptr = A + (size_t)(bm + (aload ? alrow : 0))*K + alkq;
    const float* bptr = W + (size_t)(bn + blrow)*K + blkq;

    uint64_t acc01 = 0ull, acc23 = 0ull;

    {
        if (aload) {
            float4 av = *reinterpret_cast<const float4*>(aptr);
            sm->w2.As[0][alkq+0][alrow]=av.x; sm->w2.As[0][alkq+1][alrow]=av.y;
            sm->w2.As[0][alkq+2][alrow]=av.z; sm->w2.As[0][alkq+3][alrow]=av.w;
        }
        float4 b0 = *reinterpret_cast<const float4*>(bptr);
        float4 b1 = *reinterpret_cast<const float4*>(bptr + 16);
        sm->w2.Bs[0][blkq+0][blrow]=b0.x; sm->w2.Bs[0][blkq+1][blrow]=b0.y;
        sm->w2.Bs[0][blkq+2][blrow]=b0.z; sm->w2.Bs[0][blkq+3][blrow]=b0.w;
        sm->w2.Bs[0][16+blkq+0][blrow]=b1.x; sm->w2.Bs[0][16+blkq+1][blrow]=b1.y;
        sm->w2.Bs[0][16+blkq+2][blrow]=b1.z; sm->w2.Bs[0][16+blkq+3][blrow]=b1.w;
    }
    __syncthreads();

    const int nch = K >> 5;
    for (int c = 0; c < nch; c++) {
        const int buf = c & 1;
        const bool more = (c + 1 < nch);
        float4 av2, b20, b21;
        if (more) {
            int ko = (c+1)*32;
            if (aload) av2 = *reinterpret_cast<const float4*>(aptr + ko);
            b20 = *reinterpret_cast<const float4*>(bptr + ko);
            b21 = *reinterpret_cast<const float4*>(bptr + ko + 16);
        }
        #pragma unroll
        for (int kk = 0; kk < 32; kk++) {   // strictly ascending k
            uint64_t ad = pk2(sm->w2.As[buf][kk][my]);
            ulonglong2 bp = *reinterpret_cast<const ulonglong2*>(&sm->w2.Bs[buf][kk][tx*4]);
            ffma2(acc01, ad, bp.x);
            ffma2(acc23, ad, bp.y);
        }
        if (more) {
            const int nbuf = buf ^ 1;
            if (aload) {
                sm->w2.As[nbuf][alkq+0][alrow]=av2.x; sm->w2.As[nbuf][alkq+1][alrow]=av2.y;
                sm->w2.As[nbuf][alkq+2][alrow]=av2.z; sm->w2.As[nbuf][alkq+3][alrow]=av2.w;
            }
            sm->w2.Bs[nbuf][blkq+0][blrow]=b20.x; sm->w2.Bs[nbuf][blkq+1][blrow]=b20.y;
            sm->w2.Bs[nbuf][blkq+2][blrow]=b20.z; sm->w2.Bs[nbuf][blkq+3][blrow]=b20.w;
            sm->w2.Bs[nbuf][16+blkq+0][blrow]=b21.x; sm->w2.Bs[nbuf][16+blkq+1][blrow]=b21.y;
            sm->w2.Bs[nbuf][16+blkq+2][blrow]=b21.z; sm->w2.Bs[nbuf][16+blkq+3][blrow]=b21.w;
        }
        __syncthreads();
    }
    const int m = bm + my;   // 784 = 49*16, always valid
    float2 v01 = upk(acc01);
    float2 v23 = upk(acc23);
    ep_one<MODE>(m, bn + tx*4 + 0, N, v01.x, scale, bias, mem, 0, yout);
    ep_one<MODE>(m, bn + tx*4 + 1, N, v01.y, scale, bias, mem, 0, yout);
    ep_one<MODE>(m, bn + tx*4 + 2, N, v23.x, scale, bias, mem, 0, yout);
    ep_one<MODE>(m, bn + tx*4 + 3, N, v23.y, scale, bias, mem, 0, yout);
}

// ---------------- LN: stats only (XLA vectorized-reduce order) ----------------
__device__ __forceinline__ void ln_stats_warp(const float* __restrict__ rin, float2* __restrict__ outp)
{
    const unsigned fm = 0xffffffffu;
    int lane = threadIdx.x & 31;
    float a = 0.f;
    if (lane < 4) {
        for (int t2 = 0; t2 < 96; t2++) a = __fadd_rn(a, rin[4*t2 + lane]);
    }
    float a0 = __shfl_sync(fm, a, 0), a1 = __shfl_sync(fm, a, 1);
    float a2 = __shfl_sync(fm, a, 2), a3 = __shfl_sync(fm, a, 3);
    float mean = __fdiv_rn(__fadd_rn(__fadd_rn(a0, a2), __fadd_rn(a1, a3)), 384.0f);

    float b = 0.f;
    if (lane < 4) {
        for (int t2 = 0; t2 < 96; t2++) {
            float d = __fadd_rn(rin[4*t2 + lane], -mean);
            b = __fadd_rn(b, __fmul_rn(d, d));
        }
    }
    float b0 = __shfl_sync(fm, b, 0), b1 = __shfl_sync(fm, b, 1);
    float b2 = __shfl_sync(fm, b, 2), b3 = __shfl_sync(fm, b, 3);
    float var = __fdiv_rn(__fadd_rn(__fadd_rn(b0, b2), __fadd_rn(b1, b3)), 384.0f);
    float inv = __fdiv_rn(1.0f, __fsqrt_rn(__fadd_rn(var, EPSF)));
    if (lane == 0) *outp = make_float2(mean, inv);
}

// ---------------- full LN row (final LN only) ----------------
__device__ __forceinline__ void ln_row_warp(const float* __restrict__ rin,
        const float* __restrict__ g, const float* __restrict__ bta, float* __restrict__ out)
{
    const unsigned fm = 0xffffffffu;
    int lane = threadIdx.x & 31;
    float a = 0.f;
    if (lane < 4) {
        for (int t2 = 0; t2 < 96; t2++) a = __fadd_rn(a, rin[4*t2 + lane]);
    }
    float a0 = __shfl_sync(fm, a, 0), a1 = __shfl_sync(fm, a, 1);
    float a2 = __shfl_sync(fm, a, 2), a3 = __shfl_sync(fm, a, 3);
    float mean = __fdiv_rn(__fadd_rn(__fadd_rn(a0, a2), __fadd_rn(a1, a3)), 384.0f);

    float b = 0.f;
    if (lane < 4) {
        for (int t2 = 0; t2 < 96; t2++) {
            float d = __fadd_rn(rin[4*t2 + lane], -mean);
            b = __fadd_rn(b, __fmul_rn(d, d));
        }
    }
    float b0 = __shfl_sync(fm, b, 0), b1 = __shfl_sync(fm, b, 1);
    float b2 = __shfl_sync(fm, b, 2), b3 = __shfl_sync(fm, b, 3);
    float var = __fdiv_rn(__fadd_rn(__fadd_rn(b0, b2), __fadd_rn(b1, b3)), 384.0f);
    float inv = __fdiv_rn(1.0f, __fsqrt_rn(__fadd_rn(var, EPSF)));

    for (int d = lane; d < DMODEL; d += 32) {
        float dv = __fadd_rn(rin[d], -mean);
        out[d] = __fadd_rn(__fmul_rn(__fmul_rn(dv, inv), g[d]), bta[d]);
    }
}

// ---------------- patch-embed LIF + pos (strided range) ----------------
__device__ __forceinline__ void patch_lif_range(const float* __restrict__ pos, int start, int stride)
{
    for (int i = start; i < ROWS*DMODEL; i += stride) {
        float mm = __fadd_rn(__fmul_rn(BETAF, g_mpe[i]), g_h[i]);
        float s = (mm > 1.0f) ? 1.0f : 0.0f;
        g_mpe[i] = __fadd_rn(mm, -s);
        g_y[i] = __fadd_rn(s, pos[i % (NTOK*DMODEL)]);
    }
}

// ---------------- zero helper ----------------
__device__ __forceinline__ void zero_arr(float* p, int n, int gtid, int nth)
{
    for (int i = gtid; i < n; i += nth) p[i] = 0.f;
}

// ---------------- the megakernel ----------------
__global__ void __launch_bounds__(256, 2) mega(
    const float* __restrict__ x,      const float* __restrict__ conv_w,
    const float* __restrict__ bn0_s,  const float* __restrict__ bn0_b,
    const float* __restrict__ pos,
    const float* __restrict__ Wq,     const float* __restrict__ bnq_s, const float* __restrict__ bnq_b,
    const float* __restrict__ Wk,     const float* __restrict__ bnk_s, const float* __restrict__ bnk_b,
    const float* __restrict__ Wv,     const float* __restrict__ bnv_s, const float* __restrict__ bnv_b,
    const float* __restrict__ Wo,
    const float* __restrict__ ln1_g,  const float* __restrict__ ln1_b,
    const float* __restrict__ W1,     const float* __restrict__ bn1_s, const float* __restrict__ bn1_b,
    const float* __restrict__ W2,     const float* __restrict__ bn2_s, const float* __restrict__ bn2_b,
    const float* __restrict__ ln2_g,  const float* __restrict__ ln2_b,
    const float* __restrict__ lnf_g,  const float* __restrict__ lnf_b,
    const float* __restrict__ head_w, const float* __restrict__ head_b,
    float* __restrict__ out)
{
    __shared__ SmemU sm;
    const int nb  = gridDim.x;
    const int tid = threadIdx.x;
    const int wrp = tid >> 5;
    const int gtid = blockIdx.x * 256 + tid;
    const int nth  = nb * 256;

    // ---- zero persistent state ----
    zero_arr(g_mpe, ROWS*DMODEL, gtid, nth);
    zero_arr(g_mq,  DEPTH*ROWS*DMODEL, gtid, nth);
    zero_arr(g_mk,  DEPTH*ROWS*DMODEL, gtid, nth);
    zero_arr(g_mv,  DEPTH*ROWS*DMODEL, gtid, nth);
    zero_arr(g_m1,  DEPTH*ROWS*MLPD, gtid, nth);
    zero_arr(g_m2,  DEPTH*ROWS*DMODEL, gtid, nth);
    zero_arr(g_mh,  BSZ*NCLS, gtid, nth);
    zero_arr(g_acc, BSZ*NCLS, gtid, nth);

    // ---- conv patch embed (once); Eigen tap order (kh, kw, c), c minor ----
    for (int item = blockIdx.x; item < ROWS; item += nb) {
        int b = item / NTOK, n = item % NTOK;
        int py = n / HP, px = n % HP;
        for (int idx = tid; idx < 768; idx += 256) {
            int c = idx >> 8; int rem = idx & 255; int i = rem >> 4; int j = rem & 15;
            sm.patch[idx] = x[(((size_t)b*CIN + c)*IMG + (py*PATCH + i))*IMG + (px*PATCH + j)];
        }
        __syncthreads();
        for (int d = tid; d < DMODEL; d += 256) {
            const float* wr = conv_w + (size_t)d*768;
            float acc = 0.f;
            for (int i = 0; i < PATCH; i++)
                for (int j = 0; j < PATCH; j++)
                    #pragma unroll
                    for (int c = 0; c < CIN; c++) {
                        int off = c*256 + i*16 + j;
                        acc = __fmaf_rn(sm.patch[off], wr[off], acc);
                    }
            g_h[((size_t)b*NTOK + n)*DMODEL + d] = __fadd_rn(__fmul_rn(acc, bn0_s[d]), bn0_b[d]);
        }
        __syncthreads();
    }
    gsync();

    // ---- patch-LIF for t=0 ----
    patch_lif_range(pos, gtid, nth);
    gsync();

    // ---- timestep loop ----
    for (int t = 0; t < TSTEPS; t++) {
        for (int l = 0; l < DEPTH; l++) {
            const size_t wOff  = (size_t)l * DMODEL * DMODEL;
            const size_t w1Off = (size_t)l * MLPD * DMODEL;
            const size_t memD  = (size_t)l * ROWS * DMODEL;
            const size_t memM  = (size_t)l * ROWS * MLPD;
            const float* Wq_l = Wq + wOff;   const float* Wk_l = Wk + wOff;
            const float* Wv_l = Wv + wOff;   const float* Wo_l = Wo + wOff;
            const float* W1_l = W1 + w1Off;  const float* W2_l = W2 + w1Off;
            const float* qs = bnq_s + l*DMODEL, *qb2 = bnq_b + l*DMODEL;
            const float* ks = bnk_s + l*DMODEL, *kb2 = bnk_b + l*DMODEL;
            const float* vs = bnv_s + l*DMODEL, *vb2 = bnv_b + l*DMODEL;
            const float* m1s = bn1_s + l*MLPD,  *m1b = bn1_b + l*MLPD;
            const float* m2s = bn2_s + l*DMODEL, *m2b = bn2_b + l*DMODEL;
            const float* l1g = ln1_g + l*DMODEL, *l1b = ln1_b + l*DMODEL;
            const float* l2g = ln2_g + l*DMODEL, *l2b = ln2_b + l*DMODEL;

            // LN1 stats
            for (int row = blockIdx.x*8 + wrp; row < ROWS; row += nb*8)
                ln_stats_warp(g_y + (size_t)row*DMODEL, &g_st[row]);
            gsync();

            // QKV: 3 x 78 = 234 tiles of 64x64, LN1 applied on the fly
            for (int t5 = blockIdx.x; t5 < 234; t5 += nb) {
                int which = t5 / 78, s = t5 % 78;
                int bm = (s / 6) * 64, bn = (s % 6) * 64;
                if (which == 0)
                    gemm_t64_ln(&sm, g_y, g_st, l1g, l1b, Wq_l, bm, bn, qs, qb2, g_mq + memD, g_q);
                else if (which == 1)
                    gemm_t64_ln(&sm, g_y, g_st, l1g, l1b, Wk_l, bm, bn, ks, kb2, g_mk + memD, g_k);
                else
                    gemm_t64_ln(&sm, g_y, g_st, l1g, l1b, Wv_l, bm, bn, vs, vb2, g_mv + memD, g_v);
            }
            gsync();

            // attention
            for (int item = blockIdx.x; item < 7*32; item += nb) {
                int chunk = item % 7;
                int bh = item / 7;
                int b = bh >> 3, h = bh & 7;
                int n0 = chunk * NCHUNK;
                __syncthreads();
                for (int tt = tid; tt < NTOK*2 + NCHUNK; tt += 256) {
                    int which, n;
                    if (tt < NTOK)        { which = 1; n = tt; }
                    else if (tt < 2*NTOK) { which = 2; n = tt - NTOK; }
                    else                  { which = 0; n = n0 + (tt - 2*NTOK); }
                    const float* src = (which == 0 ? g_q : (which == 1 ? g_k : g_v))
                                       + ((size_t)(b*NTOK + n))*DMODEL + h*HD;
                    unsigned long long bits = 0ull;
                    #pragma unroll
                    for (int j = 0; j < HD; j++)
                        if (src[j] != 0.f) bits |= (1ull << j);
                    if (which == 0)      sm.a.qcb[n - n0] = bits;
                    else if (which == 1) sm.a.kbv[n] = bits;
                    else                 sm.a.vbv[n] = bits;
                }
                __syncthreads();
                for (int idx = tid; idx < NCHUNK*NTOK; idx += 256) {
                    int cc = __popcll(sm.a.qcb[idx/NTOK] & sm.a.kbv[idx%NTOK]);
                    sm.a.af[idx/NTOK][idx%NTOK] = __fmul_rn((float)cc, SCALEF);
                }
                __syncthreads();
                {
                    float accv[6];
                    const float* af6[6];
                    int dd6[6];
                    int cnt = 0;
                    for (int it2 = tid; it2 < NCHUNK*HD; it2 += 256) {
                        af6[cnt] = sm.a.af[it2 / HD];
                        dd6[cnt] = it2 % HD;
                        accv[cnt] = 0.f;
                        cnt++;
                    }
                    for (int m = 0; m < NTOK; m++) {
                        unsigned long long vb = sm.a.vbv[m];
                        #pragma unroll
                        for (int i = 0; i < 6; i++) {
                            if (i < cnt) {
                                float a = af6[i][m];
                                if ((vb >> dd6[i]) & 1ull) accv[i] = __fadd_rn(accv[i], a);
                            }
                        }
                    }
                    int ci = 0;
                    for (int it2 = tid; it2 < NCHUNK*HD; it2 += 256) {
                        int n = it2 / HD, d = it2 % HD;
                        g_o[((size_t)(b*NTOK + n0 + n))*DMODEL + h*HD + d] = accv[ci++];
                    }
                }
                __syncthreads();
            }
            gsync();

            // Wo residual: 294 tiles of 16x64, KC=32
            for (int t5 = blockIdx.x; t5 < 294; t5 += nb) {
                int bm = (t5 / 6) * 16, bn = (t5 % 6) * 64;
                gemm_t16x64<1>(&sm, g_o, Wo_l, DMODEL, DMODEL, bm, bn, 0, 0, 0, g_y);
            }
            gsync();

            // LN2 stats
            for (int row = blockIdx.x*8 + wrp; row < ROWS; row += nb*8)
                ln_stats_warp(g_y + (size_t)row*DMODEL, &g_st[row]);
            gsync();

            // MLP1: 300 tiles of 32x128, LN2 on the fly
            for (int t5 = blockIdx.x; t5 < 300; t5 += nb) {
                int bm = (t5 / 12) * 32, bn = (t5 % 12) * 128;
                gemm_mlp1(&sm, g_y, g_st, l2g, l2b, W1_l, bm, bn, m1s, m1b, g_m1 + memM, g_s1);
            }
            gsync();

            // MLP2: 294 tiles of 16x64, K=1536, KC=32
            for (int t5 = blockIdx.x; t5 < 294; t5 += nb) {
                int bm = (t5 / 6) * 16, bn = (t5 % 6) * 64;
                gemm_t16x64<2>(&sm, g_s1, W2_l, DMODEL, MLPD, bm, bn, m2s, m2b, g_m2 + memD, g_y);
            }
            gsync();
        }

        // final LN (full output into xn)
        for (int row = blockIdx.x*8 + wrp; row < ROWS; row += nb*8)
            ln_row_warp(g_y + (size_t)row*DMODEL, lnf_g, lnf_b, g_xn + (size_t)row*DMODEL);
        gsync();

        // token-mean pool (serial over n ascending)
        for (int it = gtid; it < BSZ*DMODEL; it += nth) {
            int b = it / DMODEL, d = it % DMODEL;
            float acc = 0.f;
            for (int n = 0; n < NTOK; n++)
                acc = __fadd_rn(acc, g_xn[((size_t)(b*NTOK + n))*DMODEL + d]);
            g_pool[it] = __fdiv_rn(acc, 196.0f);
        }
        gsync();

        // head logits + LIF (block 0) || patch-LIF for t+1 (other blocks)
        if (blockIdx.x == 0) {
            if (tid < BSZ*NCLS) {
                int b = tid / NCLS, c = tid % NCLS;
                float acc = 0.f;
                for (int d = 0; d < DMODEL; d++)
                    acc = __fmaf_rn(g_pool[b*DMODEL + d], head_w[d*NCLS + c], acc);
                float inp = __fadd_rn(acc, head_b[c]);
                float mm = __fadd_rn(__fmul_rn(BETAF, g_mh[tid]), inp);
                float s = (mm > 1.0f) ? 1.0f : 0.0f;
                g_mh[tid] = __fadd_rn(mm, -s);
                g_acc[tid] += s;
            }
        } else if (t + 1 < TSTEPS) {
            patch_lif_range(pos, (blockIdx.x - 1)*256 + tid, (nb - 1)*256);
        }
        gsync();
    }

    if (blockIdx.x == 0 && tid < BSZ*NCLS)
        out[tid] = __fdiv_rn(g_acc[tid], (float)TSTEPS);
}

// ---------------- host ----------------
extern "C" void kernel_launch(void* const* d_in, const int* in_sizes, int n_in,
                              void* d_out, int out_size)
{
    const float* x       = (const float*)d_in[0];
    const float* conv_w  = (const float*)d_in[1];
    const float* bn0_s   = (const float*)d_in[2];
    const float* bn0_b   = (const float*)d_in[3];
    const float* pos     = (const float*)d_in[4];
    const float* Wq      = (const float*)d_in[5];
    const float* bnq_s   = (const float*)d_in[6];
    const float* bnq_b   = (const float*)d_in[7];
    const float* Wk      = (const float*)d_in[8];
    const float* bnk_s   = (const float*)d_in[9];
    const float* bnk_b   = (const float*)d_in[10];
    const float* Wv      = (const float*)d_in[11];
    const float* bnv_s   = (const float*)d_in[12];
    const float* bnv_b   = (const float*)d_in[13];
    const float* Wo      = (const float*)d_in[14];
    const float* ln1_g   = (const float*)d_in[15];
    const float* ln1_b   = (const float*)d_in[16];
    const float* W1      = (const float*)d_in[17];
    const float* bn1_s   = (const float*)d_in[18];
    const float* bn1_b   = (const float*)d_in[19];
    const float* W2      = (const float*)d_in[20];
    const float* bn2_s   = (const float*)d_in[21];
    const float* bn2_b   = (const float*)d_in[22];
    const float* ln2_g   = (const float*)d_in[23];
    const float* ln2_b   = (const float*)d_in[24];
    const float* lnf_g   = (const float*)d_in[25];
    const float* lnf_b   = (const float*)d_in[26];
    const float* head_w  = (const float*)d_in[27];
    const float* head_b  = (const float*)d_in[28];
    float* out = (float*)d_out;

    int dev = 0;
    cudaGetDevice(&dev);
    int nsm = 0;
    cudaDeviceGetAttribute(&nsm, cudaDevAttrMultiProcessorCount, dev);
    int bpm = 0;
    cudaOccupancyMaxActiveBlocksPerMultiprocessor(&bpm, mega, 256, 0);
    if (bpm < 1) bpm = 1;
    if (bpm > 2) bpm = 2;
    int nblk = nsm * bpm;

    mega<<<nblk, 256>>>(x, conv_w, bn0_s, bn0_b, pos,
                        Wq, bnq_s, bnq_b, Wk, bnk_s, bnk_b, Wv, bnv_s, bnv_b, Wo,
                        ln1_g, ln1_b, W1, bn1_s, bn1_b, W2, bn2_s, bn2_b,
                        ln2_g, ln2_b, lnf_g, lnf_b, head_w, head_b, out);
}